// round 4
// baseline (speedup 1.0000x reference)
#include <cuda_runtime.h>
#include <math.h>

#define N_NODES   100000
#define N_FEAT    128
#define N_CLASSES 40
#define N_EDGES   1600000
#define K_HOPS    2

#define SCAN_BLK  1024
#define SCAN_NB   ((N_NODES + SCAN_BLK - 1) / SCAN_BLK)   // 98

#define FILL_BLOCKS ((N_EDGES + 255) / 256)               // 6250
#define GEMM_TOTAL  (N_NODES / 2)                         // 50000 threads (2 nodes each)
#define GEMM_BLOCKS ((GEMM_TOTAL + 255) / 256)            // 196

// ---- scratch (__device__ globals; no allocation allowed) ----
__device__ float g_bufA[N_NODES * N_CLASSES];   // 16 MB
__device__ float g_bufB[N_NODES * N_CLASSES];   // 16 MB
__device__ int   g_deg[N_NODES];
__device__ float g_dis[N_NODES];
__device__ int   g_incl[N_NODES];
__device__ int   g_bsum[SCAN_NB];
__device__ int   g_boff[SCAN_NB];
__device__ int   g_rowstart[N_NODES + 1];
__device__ int   g_cursor[N_NODES];
__device__ int2  g_csr[N_EDGES];                // {src, bits(w)} 12.8 MB

// ---- fp32x2 packed helpers ------------------------------------------------
__device__ __forceinline__ unsigned long long pk2(float lo, float hi) {
    unsigned long long r;
    asm("mov.b64 %0, {%1, %2};" : "=l"(r) : "f"(lo), "f"(hi));
    return r;
}
__device__ __forceinline__ void unpk2(float& lo, float& hi, unsigned long long v) {
    asm("mov.b64 {%0, %1}, %2;" : "=f"(lo), "=f"(hi) : "l"(v));
}
__device__ __forceinline__ void fma2(unsigned long long& d, unsigned long long a,
                                     unsigned long long b) {
    asm("fma.rn.f32x2 %0, %1, %2, %0;" : "+l"(d) : "l"(a), "l"(b));
}

// ---------------------------------------------------------------------------
__global__ void k_zero_deg() {
    int i = blockIdx.x * blockDim.x + threadIdx.x;
    if (i < N_NODES) g_deg[i] = 0;
}

__global__ void k_hist(const int* __restrict__ dst, int E) {
    int e = blockIdx.x * blockDim.x + threadIdx.x;
    if (e < E) atomicAdd(&g_deg[dst[e]], 1);
}

// ---- scan stage 1: per-block inclusive scan of deg -----------------------
__global__ void k_scan1() {
    __shared__ int s[SCAN_BLK];
    int gid = blockIdx.x * SCAN_BLK + threadIdx.x;
    int v = (gid < N_NODES) ? g_deg[gid] : 0;
    s[threadIdx.x] = v;
    __syncthreads();
    for (int off = 1; off < SCAN_BLK; off <<= 1) {
        int t = (threadIdx.x >= off) ? s[threadIdx.x - off] : 0;
        __syncthreads();
        s[threadIdx.x] += t;
        __syncthreads();
    }
    if (gid < N_NODES) g_incl[gid] = s[threadIdx.x];
    if (threadIdx.x == SCAN_BLK - 1) g_bsum[blockIdx.x] = s[threadIdx.x];
}

// ---- scan stage 2: parallel scan of 98 block sums (one block) ------------
__global__ void k_scan2(int E) {
    __shared__ int s[128];
    int v = (threadIdx.x < SCAN_NB) ? g_bsum[threadIdx.x] : 0;
    s[threadIdx.x] = v;
    __syncthreads();
    for (int off = 1; off < 128; off <<= 1) {
        int t = (threadIdx.x >= off) ? s[threadIdx.x - off] : 0;
        __syncthreads();
        s[threadIdx.x] += t;
        __syncthreads();
    }
    if (threadIdx.x < SCAN_NB) g_boff[threadIdx.x] = s[threadIdx.x] - v;  // exclusive
    if (threadIdx.x == 0) g_rowstart[N_NODES] = E;
}

// ---- scan stage 3: exclusive rowstart + cursor + dis ---------------------
__global__ void k_scan3() {
    int i = blockIdx.x * blockDim.x + threadIdx.x;
    if (i >= N_NODES) return;
    int d = g_deg[i];
    int ex = g_incl[i] - d + g_boff[i / SCAN_BLK];
    g_rowstart[i] = ex;
    g_cursor[i]   = ex;
    g_dis[i] = rsqrtf((float)d + 1.0f);   // +1 = self loop
}

// ---- fused: CSR fill (blocks [0,6250)) + packed GEMM (remaining blocks) ---
// fill:  csr[p] = {src, dis[src]*dis[dst]}
// gemm:  g_bufA = x @ W, 2 nodes per thread packed into fp32x2 lanes
__global__ __launch_bounds__(256) void k_fill_gemm(const int* __restrict__ src,
                                                   const int* __restrict__ dst, int E,
                                                   const float* __restrict__ x,
                                                   const float* __restrict__ W) {
    __shared__ float2 Wp[N_CLASSES * N_FEAT];  // 40 KB, [c][k] = {w,w}

    if (blockIdx.x < FILL_BLOCKS) {
        int e = blockIdx.x * 256 + threadIdx.x;
        if (e < E) {
            int s = src[e];
            int d = dst[e];
            float w = g_dis[s] * g_dis[d];
            int p = atomicAdd(&g_cursor[d], 1);
            g_csr[p] = make_int2(s, __float_as_int(w));
        }
        return;
    }

    // ---- GEMM role ----
    for (int i = threadIdx.x; i < N_FEAT * N_CLASSES; i += 256) {
        int k = i / N_CLASSES, c = i % N_CLASSES;
        float w = W[i];
        Wp[c * N_FEAT + k] = make_float2(w, w);
    }
    __syncthreads();

    int t = (blockIdx.x - FILL_BLOCKS) * 256 + threadIdx.x;
    if (t >= GEMM_TOTAL) return;
    int n0 = t, n1 = t + GEMM_TOTAL;

    unsigned long long acc2[N_CLASSES];
#pragma unroll
    for (int c = 0; c < N_CLASSES; c++) acc2[c] = 0ULL;

    const float4* xr0 = (const float4*)(x + (size_t)n0 * N_FEAT);
    const float4* xr1 = (const float4*)(x + (size_t)n1 * N_FEAT);
    const unsigned long long* Wp64 = (const unsigned long long*)Wp;

#pragma unroll 1
    for (int k0 = 0; k0 < N_FEAT; k0 += 4) {
        float4 a = __ldg(&xr0[k0 >> 2]);
        float4 b = __ldg(&xr1[k0 >> 2]);
        unsigned long long x0 = pk2(a.x, b.x);
        unsigned long long x1 = pk2(a.y, b.y);
        unsigned long long x2 = pk2(a.z, b.z);
        unsigned long long x3 = pk2(a.w, b.w);
#pragma unroll
        for (int c = 0; c < N_CLASSES; c++) {
            const unsigned long long* wr = Wp64 + c * N_FEAT + k0;
            fma2(acc2[c], x0, wr[0]);
            fma2(acc2[c], x1, wr[1]);
            fma2(acc2[c], x2, wr[2]);
            fma2(acc2[c], x3, wr[3]);
        }
    }
    float* o0 = g_bufA + (size_t)n0 * N_CLASSES;
    float* o1 = g_bufA + (size_t)n1 * N_CLASSES;
#pragma unroll
    for (int c = 0; c < N_CLASSES; c++) {
        float lo, hi;
        unpk2(lo, hi, acc2[c]);
        o0[c] = lo;
        o1[c] = hi;
    }
}

// ---- warp-per-node gather core --------------------------------------------
// Row = 40 floats. acc0 = f[lane], acc1 = f[32+lane] (lanes 0-7 only).
__device__ __forceinline__ void gather_node(const float* __restrict__ in, int node,
                                            int lane, float& acc0, float& acc1) {
    int beg = g_rowstart[node];
    int end = g_rowstart[node + 1];
    acc0 = 0.f; acc1 = 0.f;
    bool tail = (lane < 8);

    int j = beg;
    for (; j + 4 <= end; j += 4) {
        int2 e0 = __ldg(&g_csr[j]);
        int2 e1 = __ldg(&g_csr[j + 1]);
        int2 e2 = __ldg(&g_csr[j + 2]);
        int2 e3 = __ldg(&g_csr[j + 3]);
        float w0 = __int_as_float(e0.y);
        float w1 = __int_as_float(e1.y);
        float w2 = __int_as_float(e2.y);
        float w3 = __int_as_float(e3.y);
        const float* r0 = in + (size_t)e0.x * N_CLASSES;
        const float* r1 = in + (size_t)e1.x * N_CLASSES;
        const float* r2 = in + (size_t)e2.x * N_CLASSES;
        const float* r3 = in + (size_t)e3.x * N_CLASSES;
        float v0 = __ldg(r0 + lane);
        float v1 = __ldg(r1 + lane);
        float v2 = __ldg(r2 + lane);
        float v3 = __ldg(r3 + lane);
        acc0 += w0 * v0 + w1 * v1 + w2 * v2 + w3 * v3;
        if (tail) {
            acc1 += w0 * __ldg(r0 + 32 + lane) + w1 * __ldg(r1 + 32 + lane)
                  + w2 * __ldg(r2 + 32 + lane) + w3 * __ldg(r3 + 32 + lane);
        }
    }
    for (; j < end; j++) {
        int2 e0 = __ldg(&g_csr[j]);
        float w0 = __int_as_float(e0.y);
        const float* r0 = in + (size_t)e0.x * N_CLASSES;
        acc0 += w0 * __ldg(r0 + lane);
        if (tail) acc1 += w0 * __ldg(r0 + 32 + lane);
    }
    // self-loop term
    float di = g_dis[node];
    float si = di * di;
    const float* rs = in + (size_t)node * N_CLASSES;
    acc0 += si * __ldg(rs + lane);
    if (tail) acc1 += si * __ldg(rs + 32 + lane);
}

// ---- hop 1: bufA -> bufB --------------------------------------------------
__global__ __launch_bounds__(256) void k_hop1() {
    int node = (blockIdx.x * blockDim.x + threadIdx.x) >> 5;
    int lane = threadIdx.x & 31;
    if (node >= N_NODES) return;
    float acc0, acc1;
    gather_node(g_bufA, node, lane, acc0, acc1);
    float* o = g_bufB + (size_t)node * N_CLASSES;
    o[lane] = acc0;
    if (lane < 8) o[32 + lane] = acc1;
}

// ---- hop 2 fused with bias + log_softmax: bufB -> d_out -------------------
__global__ __launch_bounds__(256) void k_hop2(const float* __restrict__ b,
                                              float* __restrict__ out) {
    int node = (blockIdx.x * blockDim.x + threadIdx.x) >> 5;
    int lane = threadIdx.x & 31;
    if (node >= N_NODES) return;
    float acc0, acc1;
    gather_node(g_bufB, node, lane, acc0, acc1);

    float l0 = acc0 + __ldg(b + lane);
    float l1 = (lane < 8) ? (acc1 + __ldg(b + 32 + lane)) : -INFINITY;

    float m = fmaxf(l0, l1);
#pragma unroll
    for (int off = 16; off > 0; off >>= 1)
        m = fmaxf(m, __shfl_xor_sync(0xFFFFFFFFu, m, off));

    float e = expf(l0 - m) + ((lane < 8) ? expf(l1 - m) : 0.f);
#pragma unroll
    for (int off = 16; off > 0; off >>= 1)
        e += __shfl_xor_sync(0xFFFFFFFFu, e, off);

    float lse = m + logf(e);
    float* o = out + (size_t)node * N_CLASSES;
    o[lane] = l0 - lse;
    if (lane < 8) o[32 + lane] = l1 - lse;
}

// ---------------------------------------------------------------------------
extern "C" void kernel_launch(void* const* d_in, const int* in_sizes, int n_in,
                              void* d_out, int out_size) {
    const float* x  = (const float*)d_in[0];
    const float* W  = (const float*)d_in[1];
    const float* b  = (const float*)d_in[2];
    const int*   ei = (const int*)d_in[3];
    // d_in[4] is K (scalar, = 2); fixed as K_HOPS.

    const int E = in_sizes[3] / 2;
    const int* src = ei;
    const int* dst = ei + E;

    const int T = 256;

    // ---- CSR build chain; GEMM overlapped inside the fill launch ----
    k_zero_deg<<<(N_NODES + T - 1) / T, T>>>();
    k_hist<<<(E + T - 1) / T, T>>>(dst, E);
    k_scan1<<<SCAN_NB, SCAN_BLK>>>();
    k_scan2<<<1, 128>>>(E);
    k_scan3<<<(N_NODES + T - 1) / T, T>>>();
    k_fill_gemm<<<FILL_BLOCKS + GEMM_BLOCKS, 256>>>(src, dst, E, x, W);

    // ---- 2 hops, warp per node; hop2 fused with bias+log_softmax ----
    const int WARPS_PER_BLK = 8;  // 256 threads
    int hop_blocks = (N_NODES + WARPS_PER_BLK - 1) / WARPS_PER_BLK;
    k_hop1<<<hop_blocks, 256>>>();
    k_hop2<<<hop_blocks, 256>>>(b, (float*)d_out);
}